// round 17
// baseline (speedup 1.0000x reference)
#include <cuda_runtime.h>
#include <cuda_fp16.h>
#include <cstdint>

#define CIN 128
#define COUT 256
#define HH 64
#define WW 64
#define KTOP 64
#define NOISE_SCALE (8.0f/255.0f)

#define NSTG 18              // K = 1152 = 18 chunks of 64 (4 x k16), tap-major
#define BAND 4.5e-3f
#define LISTCAP 512

// ---- smem layout ----
// A: [stage2][ks4][64 pix][32B]  = 16384 B at 0      (canonical k, swizzled halves)
// B: [stage2][ks4][256 co][32B]  = 65536 B at 16384  (end 81920)
// o_s overlay: 64*257 floats = 65792 B at 0
#define AS_B 0
#define BS_B 16384
#define OS_STRIDE 257
#define RB_F 20480
#define WB_F (RB_F+256)
#define TK_F (WB_F+256)
#define CNT_F (TK_F+64)
#define LIST_F (CNT_F+4)
#define SMEM_F (LIST_F+LISTCAP)
#define SMEM_BYTES (SMEM_F*4)

// prepped weights fp16, tap-major, canonical k order with half-swizzle baked in:
// byte addr = ((stage*4+ks)*256 + co)*32 + ((h ^ ((co>>2)&1))<<4) + j*2
__device__ uint2 g_wh[NSTG * 4 * COUT * 4];
__device__ float g_wbias[COUT];

__device__ __forceinline__ uint32_t smem_to_u32(const void* p) {
    uint32_t a;
    asm("{ .reg .u64 t; cvta.to.shared.u64 t, %1; cvt.u32.u64 %0, t; }" : "=r"(a) : "l"(p));
    return a;
}
__device__ __forceinline__ unsigned f2key(float v) {
    unsigned u = __float_as_uint(v);
    return (u & 0x80000000u) ? ~u : (u | 0x80000000u);
}
__device__ __forceinline__ float key2f(unsigned k) {
    unsigned u = (k & 0x80000000u) ? (k & 0x7fffffffu) : ~k;
    return __uint_as_float(u);
}
__device__ __forceinline__ unsigned h2(float lo, float hi) {
    __half2 p = __floats2half2_rn(lo, hi);
    return *(unsigned*)&p;
}

#define MMA_FP16(dv, a0, a1, a2, a3, b0, b1) \
    asm volatile("mma.sync.aligned.m16n8k16.row.col.f32.f16.f16.f32 " \
        "{%0,%1,%2,%3}, {%4,%5,%6,%7}, {%8,%9}, {%0,%1,%2,%3};" \
        : "+f"((dv)[0]), "+f"((dv)[1]), "+f"((dv)[2]), "+f"((dv)[3]) \
        : "r"(a0), "r"(a1), "r"(a2), "r"(a3), "r"(b0), "r"(b1))

#define LDMATRIX_X4(r0, r1, r2, r3, addr) \
    asm volatile("ldmatrix.sync.aligned.m8n8.x4.shared.b16 {%0,%1,%2,%3}, [%4];" \
        : "=r"(r0), "=r"(r1), "=r"(r2), "=r"(r3) : "r"(addr))

#define CP_ASYNC16(dst_u32, src_ptr) \
    asm volatile("cp.async.ca.shared.global [%0], [%1], 16;" :: "r"(dst_u32), "l"(src_ptr))
#define CP_COMMIT()  asm volatile("cp.async.commit_group;")
#define CP_WAIT0()   asm volatile("cp.async.wait_group 0;" ::: "memory")

// ---------------- merged prep kernel ----------------
__global__ void prep_all(const float* __restrict__ w) {
    __shared__ float red[128];
    int co = blockIdx.x;
    unsigned short* dst = (unsigned short*)g_wh;
    float s = 0.f;
    for (int kp = threadIdx.x; kp < 1152; kp += 128) {
        int tap = kp >> 7;
        int ci  = kp & 127;
        float v = w[co * 1152 + ci * 9 + tap];
        s += fabsf(v);
        int stage = kp >> 6;
        int ks = (kp >> 4) & 3;
        int klocal = kp & 15;
        int h = klocal >> 3, j = klocal & 7;
        int byteoff = ((stage * 4 + ks) * 256 + co) * 32
                    + ((h ^ ((co >> 2) & 1)) << 4) + j * 2;
        dst[byteoff >> 1] = __half_as_ushort(__float2half(v));
    }
    red[threadIdx.x] = s;
    __syncthreads();
    for (int off = 64; off > 0; off >>= 1) {
        if (threadIdx.x < off) red[threadIdx.x] += red[threadIdx.x + off];
        __syncthreads();
    }
    if (threadIdx.x == 0) g_wbias[co] = red[0];
}

// ---------------- main fused kernel ----------------
// CTA: 64 pixels (1 row) x 256 couts, 512 threads (16 warps), 2 CTAs/SM.
// warp (wm = wid&1, wn = wid>>1): 2 m-tiles x 4 n-tiles of m16n8k16 fp16.
__global__ void __launch_bounds__(512, 2)
conv_mma_kernel(const float* __restrict__ x, const float* __restrict__ w,
                const float* __restrict__ rbias,
                const float* __restrict__ noise, float* __restrict__ out) {
    extern __shared__ float smem[];
    char* smc = (char*)smem;
    const uint32_t smem_base = smem_to_u32(smem);
    const int t   = threadIdx.x;
    const int wid = t >> 5;
    const int lid = t & 31;
    const int g   = lid >> 2;
    const int tig = lid & 3;
    const int b   = blockIdx.y;
    const int y0  = blockIdx.x;          // one row of 64 pixels

    const int wm = wid & 1;
    const int wn = wid >> 1;

    float* rb_s = smem + RB_F;
    float* wb_s = smem + WB_F;
    unsigned* tkey_s = (unsigned*)(smem + TK_F);
    int* cnt_s = (int*)(smem + CNT_F);
    int* list_s = (int*)(smem + LIST_F);
    if (t < 256) { rb_s[t] = rbias[t]; wb_s[t] = g_wbias[t]; }
    if (t == 0) cnt_s[0] = 0;

    float d[2][4][4];
#pragma unroll
    for (int i = 0; i < 2; i++)
#pragma unroll
        for (int j = 0; j < 4; j++)
#pragma unroll
            for (int q = 0; q < 4; q++) d[i][j][q] = 0.f;

    // ldmatrix lane offsets (within a (stage,ks) tile), swizzle h^=(row>>2)&1
    const int arow = wm * 32 + (lid & 7) + ((lid >> 3) & 1) * 8;
    const int ah_  = lid >> 4;
    const uint32_t a_laneoff = (uint32_t)(arow * 32 + ((ah_ ^ ((arow >> 2) & 1)) << 4));
    const int brow = wn * 32 + (lid & 7) + ((lid >> 4) & 1) * 8;
    const int bh_  = (lid >> 3) & 1;
    const uint32_t b_laneoff = (uint32_t)(brow * 32 + ((bh_ ^ ((brow >> 2) & 1)) << 4));

    // A-build mapping: t = aks*128 + ahb*64 + pixel  (lanes = 32 consecutive pixels)
    const int ap  = t & 63;
    const int ahb = (t >> 6) & 1;
    const int aks = t >> 7;
    const float* xb = x + ((size_t)b << 19);

    auto a_build_load = [&](int c, float v[8]) {
        int tap = c >> 1;
        int kh = (tap * 11) >> 5;
        int kw = tap - 3 * kh;
        int y  = y0 + kh - 1;
        int xx = ap + kw - 1;
        bool ok = ((unsigned)y < HH) && ((unsigned)xx < WW);
        const float* xp = xb + (((c & 1) * 64 + aks * 16 + ahb * 8) << 12) + (y << 6) + xx;
#pragma unroll
        for (int j = 0; j < 8; j++) v[j] = ok ? __ldg(xp + (j << 12)) : 0.f;
    };
    auto a_store = [&](int stg, float v[8]) {
        uint32_t off = (uint32_t)((stg * 4 + aks) * 2048 + ap * 32
                     + ((ahb ^ ((ap >> 2) & 1)) << 4));
        uint4 pk;
        pk.x = h2(v[0], v[1]); pk.y = h2(v[2], v[3]);
        pk.z = h2(v[4], v[5]); pk.w = h2(v[6], v[7]);
        *(uint4*)(smc + AS_B + off) = pk;
    };

    // ---- prologue: stage 0
    {
        const char* bsrc = (const char*)g_wh;
#pragma unroll
        for (int it = 0; it < 4; it++) {
            int i = it * 512 + t;
            CP_ASYNC16(smem_base + (uint32_t)(BS_B + i * 16), bsrc + i * 16);
        }
        CP_COMMIT();
        float v[8];
        a_build_load(0, v);
        a_store(0, v);
        CP_WAIT0();
        __syncthreads();
    }

    for (int c = 0; c < NSTG; c++) {
        const int cur = c & 1, nxt = cur ^ 1;
        const bool pf = (c < NSTG - 1);
        if (pf) {
            const char* bsrc = (const char*)(g_wh + (size_t)(c + 1) * 4 * COUT * 4);
#pragma unroll
            for (int it = 0; it < 4; it++) {
                int i = it * 512 + t;
                CP_ASYNC16(smem_base + (uint32_t)(BS_B + nxt * 32768 + i * 16), bsrc + i * 16);
            }
            CP_COMMIT();
        }
        float v[8];
        if (pf) a_build_load(c + 1, v);
        // ---- compute: 4 k16-halves, ldmatrix.x4 fragments
#pragma unroll
        for (int ks = 0; ks < 4; ks++) {
            uint32_t ab = smem_base + (uint32_t)(AS_B + (cur * 4 + ks) * 2048) + a_laneoff;
            uint32_t bb = smem_base + (uint32_t)(BS_B + (cur * 4 + ks) * 8192) + b_laneoff;
            uint32_t a0[4], a1[4], b01[4], b23[4];
            LDMATRIX_X4(a0[0], a0[1], a0[2], a0[3], ab);
            LDMATRIX_X4(a1[0], a1[1], a1[2], a1[3], ab + 512);
            LDMATRIX_X4(b01[0], b01[1], b01[2], b01[3], bb);
            LDMATRIX_X4(b23[0], b23[1], b23[2], b23[3], bb + 512);
            MMA_FP16(d[0][0], a0[0], a0[1], a0[2], a0[3], b01[0], b01[1]);
            MMA_FP16(d[1][0], a1[0], a1[1], a1[2], a1[3], b01[0], b01[1]);
            MMA_FP16(d[0][1], a0[0], a0[1], a0[2], a0[3], b01[2], b01[3]);
            MMA_FP16(d[1][1], a1[0], a1[1], a1[2], a1[3], b01[2], b01[3]);
            MMA_FP16(d[0][2], a0[0], a0[1], a0[2], a0[3], b23[0], b23[1]);
            MMA_FP16(d[1][2], a1[0], a1[1], a1[2], a1[3], b23[0], b23[1]);
            MMA_FP16(d[0][3], a0[0], a0[1], a0[2], a0[3], b23[2], b23[3]);
            MMA_FP16(d[1][3], a1[0], a1[1], a1[2], a1[3], b23[2], b23[3]);
        }
        if (pf) {
            a_store(nxt, v);
            CP_WAIT0();
        }
        __syncthreads();
    }

    // ---- epilogue: spill accums to o_s[p*257 + co]
    float* o_s = smem;
#pragma unroll
    for (int mt = 0; mt < 2; mt++) {
#pragma unroll
        for (int nt = 0; nt < 4; nt++) {
            int p  = wm * 32 + mt * 16 + g;
            int co = wn * 32 + nt * 8 + 2 * tig;
            o_s[p * OS_STRIDE + co]           = d[mt][nt][0];
            o_s[p * OS_STRIDE + co + 1]       = d[mt][nt][1];
            o_s[(p + 8) * OS_STRIDE + co]     = d[mt][nt][2];
            o_s[(p + 8) * OS_STRIDE + co + 1] = d[mt][nt][3];
        }
    }
    __syncthreads();

    // ---- noise inject
#pragma unroll 4
    for (int it = 0; it < 32; it++) {
        int i  = it * 512 + t;
        int co = i >> 6;
        int p  = i & 63;
        float u = noise[((b * COUT + co) << 12) + (y0 << 6) + p];
        o_s[p * OS_STRIDE + co] += wb_s[co] * (NOISE_SCALE * (2.f * u - 1.f));
    }
    __syncthreads();

    // ---- pass 1: approx kth (bits 31..9), 4 pixels per warp, 2 independent
    //      packed REDUX chains; fused band collect
    {
        int p0 = wid * 4;
        unsigned kk[4][8];
#pragma unroll
        for (int pp = 0; pp < 4; pp++)
#pragma unroll
            for (int m = 0; m < 8; m++)
                kk[pp][m] = f2key(o_s[(p0 + pp) * OS_STRIDE + lid + 32 * m]);
        unsigned r[4] = {0u, 0u, 0u, 0u};
        for (int bit = 31; bit >= 9; bit--) {
            unsigned c0 = r[0] | (1u << bit), c1 = r[1] | (1u << bit);
            unsigned c2 = r[2] | (1u << bit), c3 = r[3] | (1u << bit);
            unsigned s01 = 0, s23 = 0;
#pragma unroll
            for (int m = 0; m < 8; m++) {
                s01 += (kk[0][m] >= c0) + ((kk[1][m] >= c1) << 16);
                s23 += (kk[2][m] >= c2) + ((kk[3][m] >= c3) << 16);
            }
            s01 = __reduce_add_sync(0xffffffffu, s01);
            s23 = __reduce_add_sync(0xffffffffu, s23);
            if ((s01 & 0xffffu) >= KTOP) r[0] = c0;
            if ((s01 >> 16)     >= KTOP) r[1] = c1;
            if ((s23 & 0xffffu) >= KTOP) r[2] = c2;
            if ((s23 >> 16)     >= KTOP) r[3] = c3;
        }
        if (lid == 0) {
            tkey_s[p0] = r[0]; tkey_s[p0+1] = r[1];
            tkey_s[p0+2] = r[2]; tkey_s[p0+3] = r[3];
        }
#pragma unroll
        for (int pp = 0; pp < 4; pp++) {
            float tv = key2f(r[pp]);
            unsigned klo = f2key(tv - BAND), khi = f2key(tv + BAND);
#pragma unroll
            for (int m = 0; m < 8; m++) {
                if (kk[pp][m] >= klo && kk[pp][m] <= khi) {
                    int idx = atomicAdd(cnt_s, 1);
                    if (idx < LISTCAP) list_s[idx] = ((p0 + pp) << 8) | (lid + 32 * m);
                }
            }
        }
    }
    __syncthreads();

    // ---- exact fp32 recompute of band elements (one warp per element)
    {
        int cnt = min(cnt_s[0], LISTCAP);
        for (int e = wid; e < cnt; e += 16) {
            int pc = list_s[e];
            int p  = pc >> 8;
            int co = pc & 255;
            float acc = 0.f;
#pragma unroll
            for (int j = 0; j < 36; j++) {
                int k = lid + 32 * j;
                int ci = (k * 7282) >> 16;
                int r9 = k - 9 * ci;
                int kh = (r9 * 11) >> 5;
                int kw = r9 - 3 * kh;
                int y  = y0 + kh - 1;
                int xx = (p & 63) + kw - 1;
                float xv = ((unsigned)y < HH && (unsigned)xx < WW)
                           ? x[((b * CIN + ci) << 12) + (y << 6) + xx] : 0.f;
                acc += xv * w[co * 1152 + k];
            }
#pragma unroll
            for (int off = 16; off > 0; off >>= 1)
                acc += __shfl_xor_sync(0xffffffffu, acc, off);
            if (lid == 0) {
                float u = noise[((b * COUT + co) << 12) + (y0 << 6) + p];
                o_s[p * OS_STRIDE + co] = acc + wb_s[co] * (NOISE_SCALE * (2.f * u - 1.f));
            }
        }
    }
    __syncthreads();

    // ---- pass 2: exact kth on corrected values, prefix-narrowed, 4-pixel ILP
    {
        int p0 = wid * 4;
        unsigned kk[4][8];
        unsigned klo[4];
        int hb = 0;
#pragma unroll
        for (int pp = 0; pp < 4; pp++) {
            float tv = key2f(tkey_s[p0 + pp]);
            klo[pp] = f2key(tv - 2.f * BAND);
            unsigned khi = f2key(tv + 2.f * BAND);
            int h = 31 - __clz((klo[pp] ^ khi) | 1);
            if (h > hb) hb = h;
#pragma unroll
            for (int m = 0; m < 8; m++)
                kk[pp][m] = f2key(o_s[(p0 + pp) * OS_STRIDE + lid + 32 * m]);
        }
        unsigned maskhi = (hb >= 31) ? 0u : ~((2u << hb) - 1u);
        unsigned r[4];
#pragma unroll
        for (int pp = 0; pp < 4; pp++) r[pp] = klo[pp] & maskhi;
        for (int bit = hb; bit >= 0; bit--) {
            unsigned c0 = r[0] | (1u << bit), c1 = r[1] | (1u << bit);
            unsigned c2 = r[2] | (1u << bit), c3 = r[3] | (1u << bit);
            unsigned s01 = 0, s23 = 0;
#pragma unroll
            for (int m = 0; m < 8; m++) {
                s01 += (kk[0][m] >= c0) + ((kk[1][m] >= c1) << 16);
                s23 += (kk[2][m] >= c2) + ((kk[3][m] >= c3) << 16);
            }
            s01 = __reduce_add_sync(0xffffffffu, s01);
            s23 = __reduce_add_sync(0xffffffffu, s23);
            if ((s01 & 0xffffu) >= KTOP) r[0] = c0;
            if ((s01 >> 16)     >= KTOP) r[1] = c1;
            if ((s23 & 0xffffu) >= KTOP) r[2] = c2;
            if ((s23 >> 16)     >= KTOP) r[3] = c3;
        }
        if (lid == 0) {
            tkey_s[p0] = r[0]; tkey_s[p0+1] = r[1];
            tkey_s[p0+2] = r[2]; tkey_s[p0+3] = r[3];
        }
    }
    __syncthreads();

    // ---- threshold (>= keeps ties) + relu_bias + relu, coalesced store
#pragma unroll 4
    for (int it = 0; it < 32; it++) {
        int i  = it * 512 + t;
        int co = i >> 6;
        int p  = i & 63;
        float vv = o_s[p * OS_STRIDE + co];
        float r = (f2key(vv) >= tkey_s[p]) ? vv : 0.f;
        r = fmaxf(r + rb_s[co], 0.f);
        out[((b * COUT + co) << 12) + (y0 << 6) + p] = r;
    }
}

extern "C" void kernel_launch(void* const* d_in, const int* in_sizes, int n_in,
                              void* d_out, int out_size) {
    const float* x  = (const float*)d_in[0];
    const float* w  = (const float*)d_in[1];
    const float* rb = (const float*)d_in[2];
    const float* nu = (const float*)d_in[3];
    float* out = (float*)d_out;

    cudaFuncSetAttribute(conv_mma_kernel,
                         cudaFuncAttributeMaxDynamicSharedMemorySize, SMEM_BYTES);

    prep_all<<<256, 128>>>(w);
    conv_mma_kernel<<<dim3(64, 32), 512, SMEM_BYTES>>>(x, w, rb, nu, out);
}